// round 2
// baseline (speedup 1.0000x reference)
#include <cuda_runtime.h>
#include <cstdint>

#define THREADS 256

// One block per (query, tensor). blockIdx.x = b*512 + n, blockIdx.y = tensor 0..2.
// Sums rows [s, e) of value[tensor][b] with float4-coalesced loads, divides by
// count, writes the 128/256-channel slice of out[b, n, :512].
__global__ void __launch_bounds__(THREADS, 8)
inform_pool_kernel(
    const float* __restrict__ v0, const float* __restrict__ v1,
    const float* __restrict__ v2,
    const float* __restrict__ start, const float* __restrict__ dur,
    float* __restrict__ out)
{
    const int q = blockIdx.x;       // 0..4095
    const int b = q >> 9;           // / 512
    const int n = q & 511;
    const int tensor = blockIdx.y;  // 0,1,2

    const float* v;
    int T, C, chOff, vshift;        // vshift: log2(C/4)
    float ratio;
    if (tensor == 0)      { v = v0; T = 16384; C = 128; ratio = 1.0f;  chOff = 0;   vshift = 5; }
    else if (tensor == 1) { v = v1; T = 8192;  C = 128; ratio = 0.5f;  chOff = 128; vshift = 5; }
    else                  { v = v2; T = 4096;  C = 256; ratio = 0.25f; chOff = 256; vshift = 6; }

    const float st = start[b * 512 + n];
    const float du = dur[b * 512 + n];

    // Match reference fp32 op order exactly:
    //   s = min(floor(start*ratio), T-1)
    //   e = min(ceil((start + duration + 1e-3)*ratio), T-1)
    int s = (int)floorf(st * ratio);
    if (s > T - 1) s = T - 1;
    int e = (int)ceilf((st + du + 1e-3f) * ratio);
    if (e > T - 1) e = T - 1;
    const int cnt = e - s;

    const int vec = C >> 2;                    // float4 lanes per row: 32 or 64
    const int rows_per_iter = THREADS >> vshift; // 8 (C=128) or 4 (C=256)
    const int rg = threadIdx.x >> vshift;      // row-group within iteration
    const int vi = threadIdx.x & (vec - 1);    // float4 index within row

    float4 acc = make_float4(0.f, 0.f, 0.f, 0.f);
    if (cnt > 0) {
        const float4* base =
            (const float4*)(v) + ((size_t)b * T) * (size_t)vec;
        for (int r = s + rg; r < e; r += rows_per_iter) {
            float4 x = __ldg(base + (size_t)r * vec + vi);
            acc.x += x.x; acc.y += x.y; acc.z += x.z; acc.w += x.w;
        }
    }

    __shared__ float4 smem[THREADS];
    smem[threadIdx.x] = acc;
    __syncthreads();

    if (rg == 0) {
        float4 tot = smem[vi];
        #pragma unroll 8
        for (int g = 1; g < rows_per_iter; g++) {
            float4 x = smem[g * vec + vi];
            tot.x += x.x; tot.y += x.y; tot.z += x.z; tot.w += x.w;
        }
        const float inv = (cnt > 0) ? (1.0f / (float)cnt) : 0.0f;
        float4 res = make_float4(tot.x * inv, tot.y * inv, tot.z * inv, tot.w * inv);
        // out: [8, 512, 512]
        float4* op = (float4*)(out + ((size_t)(b * 512 + n)) * 512 + chOff);
        op[vi] = res;
    }
}

extern "C" void kernel_launch(void* const* d_in, const int* in_sizes, int n_in,
                              void* d_out, int out_size) {
    const float* v0 = (const float*)d_in[0];  // [8, 16384, 128]
    const float* v1 = (const float*)d_in[1];  // [8, 8192, 128]
    const float* v2 = (const float*)d_in[2];  // [8, 4096, 256]
    const float* st = (const float*)d_in[3];  // [8, 512]
    const float* du = (const float*)d_in[4];  // [8, 512]

    dim3 grid(4096, 3);
    inform_pool_kernel<<<grid, THREADS>>>(v0, v1, v2, st, du, (float*)d_out);
}